// round 6
// baseline (speedup 1.0000x reference)
#include <cuda_runtime.h>

// ===================== Problem constants =====================
// M=3, N=8, G=8, K=3
// x: (32, 3, 224, 224) f32   w: (24, 1, 3, 3) f32
// out: (32, 192, 222, 222) f32, grouped conv: out channel o uses in channel o/64

#define IMG 224
#define OUT 222
#define NCH 192
#define PLANE_OUT (OUT*OUT)        // 49284  (x4B = 197136 ≡ 0 mod 16)

typedef unsigned long long u64;

// rotated weights, duplicated (w,w) pairs, padded row-aligned layout:
// g_rotw2[o*12 + dy*4 + dx], dx<3 real, dx==3 zero pad -> each dy row 16B-aligned
__device__ u64 g_rotw2[192 * 12];

__device__ __forceinline__ u64 ffma2(u64 a, u64 b, u64 c) {
    u64 d;
    asm("fma.rn.f32x2 %0, %1, %2, %3;" : "=l"(d) : "l"(a), "l"(b), "l"(c));
    return d;
}
__device__ __forceinline__ u64 pack2(float lo, float hi) {
    u64 d;
    asm("mov.b64 %0, {%1, %2};" : "=l"(d) : "f"(lo), "f"(hi));
    return d;
}

// ===================== Kernel 1: rotate weights =====================
__global__ void rotw_kernel(const float* __restrict__ w) {
    int t = blockIdx.x * blockDim.x + threadIdx.x;
    if (t >= 192 * 12) return;
    int o  = t / 12, j = t % 12;
    int dy = j >> 2, dx = j & 3;
    if (dx == 3) { g_rotw2[t] = 0ull; return; }   // pad slot
    int mn = o >> 3, g = o & 7;

    double ang = (-90.0 + (180.0 / 7.0) * (double)g) * 0.017453292519943295;
    float c = (float)cos(ang);
    float s = (float)sin(ang);

    float cx = (2.0f * dx + 1.0f) / 3.0f - 1.0f;
    float cy = (2.0f * dy + 1.0f) / 3.0f - 1.0f;
    float gx = c * cx - s * cy;
    float gy = s * cx + c * cy;

    float ix = ((gx + 1.0f) * 3.0f - 1.0f) * 0.5f;
    float iy = ((gy + 1.0f) * 3.0f - 1.0f) * 0.5f;
    float x0f = floorf(ix), y0f = floorf(iy);
    int   x0  = (int)x0f,   y0  = (int)y0f;
    float wx1 = ix - x0f, wy1 = iy - y0f;
    float wx0 = 1.0f - wx1, wy0 = 1.0f - wy1;

    const float* wp = w + mn * 9;
    float v00 = 0.f, v10 = 0.f, v01 = 0.f, v11 = 0.f;
    int x1 = x0 + 1, y1 = y0 + 1;
    bool bx0 = (x0 >= 0 && x0 < 3), bx1 = (x1 >= 0 && x1 < 3);
    bool by0 = (y0 >= 0 && y0 < 3), by1 = (y1 >= 0 && y1 < 3);
    if (bx0 && by0) v00 = wp[y0 * 3 + x0];
    if (bx1 && by0) v10 = wp[y0 * 3 + x1];
    if (bx0 && by1) v01 = wp[y1 * 3 + x0];
    if (bx1 && by1) v11 = wp[y1 * 3 + x1];

    float v = v00 * (wx0 * wy0) + v10 * (wx1 * wy0)
            + v01 * (wx0 * wy1) + v11 * (wx1 * wy1);

    g_rotw2[t] = pack2(v, v);
}

// ===================== Kernel 2: grouped conv =====================
// CTA: 128 threads = 16 col-threads x 8 row-threads. Thread: 4 cols x 4 rows.
// Tile 64x32 per CTA, 32 channels (half-group) per CTA.
#define TW 64
#define TH 32
#define IN_W 68    // 64 + 2 halo, padded so every row is 16B-aligned (68*4=272≡0 mod 16)
#define IN_H 34
#define CPC 32

__global__ void __launch_bounds__(128)
conv_kernel(const float* __restrict__ x, float* __restrict__ out) {
    __shared__ __align__(16) float s_in[IN_H * IN_W];   // 9248 B
    __shared__ __align__(16) u64   s_w[CPC * 12];       // 3072 B

    int z    = blockIdx.z;         // (n*3+m)*2 + half
    int half = z & 1;
    int nm   = z >> 1;
    int m    = nm % 3;
    int tx0  = blockIdx.x * TW;
    int ty0  = blockIdx.y * TH;
    int tid  = threadIdx.x;

    const float* xp = x + (size_t)nm * (IMG * IMG);

    // cooperative clamped input tile load (clamped junk only feeds invalid outputs)
    for (int i = tid; i < IN_H * IN_W; i += 128) {
        int r  = i / IN_W, cc = i % IN_W;
        int gr = ty0 + r;  if (gr > IMG - 1) gr = IMG - 1;
        int gc = tx0 + cc; if (gc > IMG - 1) gc = IMG - 1;
        s_in[i] = xp[gr * IMG + gc];
    }
    // weights for this half-group (padded (w,w)-pair layout)
    {
        const u64* gw = g_rotw2 + (size_t)(m * 64 + half * CPC) * 12;
        for (int i = tid; i < CPC * 12; i += 128) s_w[i] = gw[i];
    }
    __syncthreads();

    int tcol = tid & 15;           // 0..15
    int trow = tid >> 4;           // 0..7
    int lx = 4 * tcol;             // local col (mult of 4)
    int ly = 4 * trow;             // local row (even)
    int ox = tx0 + lx;             // mult of 4
    int oy = ty0 + ly;             // even
    if (ox >= OUT || oy >= OUT) return;
    bool v4  = (ox + 3) < OUT;                 // full 4-col vector valid (else cols 220-221 pair)
    bool rv1 = (oy + 1) < OUT;
    bool rv2 = (oy + 2) < OUT;
    bool rv3 = (oy + 3) < OUT;

    // Precompute all input pairs for 6 rows x 5 overlapping pairs.
    // Row r floats f0..f5 = s_in[(ly+r)*68 + lx .. +5]; pairs p[k]=(f_k,f_{k+1}).
    u64 p[6][5];
#pragma unroll
    for (int r = 0; r < 6; r++) {
        const float* rowp = &s_in[(ly + r) * IN_W + lx];     // 16B aligned
        float4 q = *(const float4*)rowp;                      // f0..f3
        float  f4 = rowp[4], f5 = rowp[5];
        p[r][0] = pack2(q.x, q.y);
        p[r][1] = pack2(q.y, q.z);
        p[r][2] = pack2(q.z, q.w);
        p[r][3] = pack2(q.w, f4);
        p[r][4] = pack2(f4, f5);
    }

    int n = nm / 3;
    float* outp = out + (size_t)(n * NCH + m * 64 + half * CPC) * PLANE_OUT
                      + (size_t)oy * OUT + ox;

#pragma unroll 1
    for (int c = 0; c < CPC; c++) {
        const u64* wc = &s_w[c * 12];
        u64 a00 = 0, a01 = 0, a10 = 0, a11 = 0;
        u64 a20 = 0, a21 = 0, a30 = 0, a31 = 0;
#pragma unroll
        for (int dy = 0; dy < 3; dy++) {
            // 16B-aligned weight row: LDS.128 (w0,w1) + LDS.64 (w2), broadcast
            ulonglong2 wab = *(const ulonglong2*)(wc + dy * 4);
            u64 w0 = wab.x, w1 = wab.y;
            u64 w2 = wc[dy * 4 + 2];
            // out pair0 (cols 0-1): taps p[.][0],p[.][1],p[.][2]
            a00 = ffma2(p[0 + dy][0], w0, a00);
            a10 = ffma2(p[1 + dy][0], w0, a10);
            a20 = ffma2(p[2 + dy][0], w0, a20);
            a30 = ffma2(p[3 + dy][0], w0, a30);
            a00 = ffma2(p[0 + dy][1], w1, a00);
            a10 = ffma2(p[1 + dy][1], w1, a10);
            a20 = ffma2(p[2 + dy][1], w1, a20);
            a30 = ffma2(p[3 + dy][1], w1, a30);
            a00 = ffma2(p[0 + dy][2], w2, a00);
            a10 = ffma2(p[1 + dy][2], w2, a10);
            a20 = ffma2(p[2 + dy][2], w2, a20);
            a30 = ffma2(p[3 + dy][2], w2, a30);
            // out pair1 (cols 2-3): taps p[.][2],p[.][3],p[.][4]
            a01 = ffma2(p[0 + dy][2], w0, a01);
            a11 = ffma2(p[1 + dy][2], w0, a11);
            a21 = ffma2(p[2 + dy][2], w0, a21);
            a31 = ffma2(p[3 + dy][2], w0, a31);
            a01 = ffma2(p[0 + dy][3], w1, a01);
            a11 = ffma2(p[1 + dy][3], w1, a11);
            a21 = ffma2(p[2 + dy][3], w1, a21);
            a31 = ffma2(p[3 + dy][3], w1, a31);
            a01 = ffma2(p[0 + dy][4], w2, a01);
            a11 = ffma2(p[1 + dy][4], w2, a11);
            a21 = ffma2(p[2 + dy][4], w2, a21);
            a31 = ffma2(p[3 + dy][4], w2, a31);
        }

        if (v4) {
            // even rows (oy, oy+2): 16B-aligned -> STG.128; odd rows: 2x STG.64
            *(ulonglong2*)(outp) = make_ulonglong2(a00, a01);
            if (rv1) { *(u64*)(outp + OUT) = a10; *(u64*)(outp + OUT + 2) = a11; }
            if (rv2) { *(ulonglong2*)(outp + 2 * OUT) = make_ulonglong2(a20, a21); }
            if (rv3) { *(u64*)(outp + 3 * OUT) = a30; *(u64*)(outp + 3 * OUT + 2) = a31; }
        } else {
            // ox == 220: only first pair valid (OUT=222)
            *(u64*)(outp) = a00;
            if (rv1) *(u64*)(outp + OUT)     = a10;
            if (rv2) *(u64*)(outp + 2 * OUT) = a20;
            if (rv3) *(u64*)(outp + 3 * OUT) = a30;
        }
        outp += PLANE_OUT;
    }
}

// ===================== launch =====================
extern "C" void kernel_launch(void* const* d_in, const int* in_sizes, int n_in,
                              void* d_out, int out_size) {
    const float* x = (const float*)d_in[0];
    const float* w = (const float*)d_in[1];
    float* out = (float*)d_out;

    rotw_kernel<<<9, 256>>>(w);   // 192*12 = 2304 slots

    dim3 grid((OUT + TW - 1) / TW,   // 4
              (OUT + TH - 1) / TH,   // 7
              32 * 3 * 2);           // 192
    conv_kernel<<<grid, 128>>>(x, out);
}

// round 7
// speedup vs baseline: 1.5380x; 1.5380x over previous
#include <cuda_runtime.h>

// ===================== Problem constants =====================
// M=3, N=8, G=8, K=3
// x: (32, 3, 224, 224) f32   w: (24, 1, 3, 3) f32
// out: (32, 192, 222, 222) f32, grouped conv: out channel o uses in channel o/64

#define IMG 224
#define OUT 222
#define NCH 192
#define PLANE_OUT (OUT*OUT)        // 49284

typedef unsigned long long u64;

// duplicated rotated weights: (w,w) packed as u64, layout [192][9]
__device__ u64 g_rotw2[192 * 9];

__device__ __forceinline__ u64 ffma2(u64 a, u64 b, u64 c) {
    u64 d;
    asm("fma.rn.f32x2 %0, %1, %2, %3;" : "=l"(d) : "l"(a), "l"(b), "l"(c));
    return d;
}
__device__ __forceinline__ u64 pack2(float lo, float hi) {
    u64 d;
    asm("mov.b64 %0, {%1, %2};" : "=l"(d) : "f"(lo), "f"(hi));
    return d;
}
__device__ __forceinline__ void unpack2(u64 v, float& lo, float& hi) {
    asm("mov.b64 {%0, %1}, %2;" : "=f"(lo), "=f"(hi) : "l"(v));
}

// ===================== Kernel 1: rotate weights =====================
__global__ void rotw_kernel(const float* __restrict__ w) {
    int t = blockIdx.x * blockDim.x + threadIdx.x;
    if (t >= 192 * 9) return;
    int o  = t / 9, j = t % 9;
    int mn = o >> 3, g = o & 7;
    int hh = j / 3, ww = j % 3;

    // angle: linspace(-90, 90, 8)[g] degrees -> radians (double, like numpy)
    double ang = (-90.0 + (180.0 / 7.0) * (double)g) * 0.017453292519943295;
    float c = (float)cos(ang);
    float s = (float)sin(ang);

    float cx = (2.0f * ww + 1.0f) / 3.0f - 1.0f;
    float cy = (2.0f * hh + 1.0f) / 3.0f - 1.0f;
    float gx = c * cx - s * cy;
    float gy = s * cx + c * cy;

    float ix = ((gx + 1.0f) * 3.0f - 1.0f) * 0.5f;
    float iy = ((gy + 1.0f) * 3.0f - 1.0f) * 0.5f;
    float x0f = floorf(ix), y0f = floorf(iy);
    int   x0  = (int)x0f,   y0  = (int)y0f;
    float wx1 = ix - x0f, wy1 = iy - y0f;
    float wx0 = 1.0f - wx1, wy0 = 1.0f - wy1;

    const float* wp = w + mn * 9;
    float v00 = 0.f, v10 = 0.f, v01 = 0.f, v11 = 0.f;
    int x1 = x0 + 1, y1 = y0 + 1;
    bool bx0 = (x0 >= 0 && x0 < 3), bx1 = (x1 >= 0 && x1 < 3);
    bool by0 = (y0 >= 0 && y0 < 3), by1 = (y1 >= 0 && y1 < 3);
    if (bx0 && by0) v00 = wp[y0 * 3 + x0];
    if (bx1 && by0) v10 = wp[y0 * 3 + x1];
    if (bx0 && by1) v01 = wp[y1 * 3 + x0];
    if (bx1 && by1) v11 = wp[y1 * 3 + x1];

    float v = v00 * (wx0 * wy0) + v10 * (wx1 * wy0)
            + v01 * (wx0 * wy1) + v11 * (wx1 * wy1);

    g_rotw2[t] = pack2(v, v);
}

// ===================== Kernel 2: grouped conv, FULL-WIDTH tiles =====================
// CTA: 224 threads = 112 x-threads x 2 y-threads. Tile = full 222-wide x 8 rows,
// all 64 channels of group m. Thread: 1 col-pair x 4 rows (R3 micro-kernel).
// Stores form one fully-contiguous 888*8 B slab per channel plane per CTA ->
// sector-complete DRAM writes (no cross-CTA partial sectors).
#define TH 8
#define IN_H 10    // 8 + 2 halo rows
// input tile rows are full 224-wide image rows: no x halo, no x clamp

__global__ void __launch_bounds__(224)
conv_kernel(const float* __restrict__ x, float* __restrict__ out) {
    __shared__ __align__(16) float s_in[IN_H * IMG];   // 10*224*4 = 8960 B
    __shared__ __align__(16) u64   s_w[64 * 9];        // 4608 B

    int nm  = blockIdx.z;          // n*3 + m
    int m   = nm % 3;
    int ty0 = blockIdx.y * TH;     // first output row of tile
    int tid = threadIdx.x;

    const float* xp = x + (size_t)nm * (IMG * IMG);

    // cooperative input load: 224 threads = exactly one full row per pass,
    // perfectly coalesced 896B. Row clamp only (last tile), never x clamp.
    for (int i = tid; i < IN_H * IMG; i += 224) {
        int r  = i / IMG, cc = i % IMG;
        int gr = ty0 + r;  if (gr > IMG - 1) gr = IMG - 1;
        s_in[i] = xp[gr * IMG + cc];
    }
    // weights for this group (duplicated (w,w) pairs)
    {
        const u64* gw = g_rotw2 + m * 64 * 9;
        for (int i = tid; i < 64 * 9; i += 224) s_w[i] = gw[i];
    }
    __syncthreads();

    int xi = tid % 112;            // col-pair index
    int yi = tid / 112;            // 0..1
    if (xi >= 111) return;         // pair 111 would be cols 222-223 (invalid); no syncs follow
    int ox = 2 * xi;
    int ly = 4 * yi;               // local first row (0 or 4)
    int oy = ty0 + ly;             // oy <= 216+4 = 220 < 222, and oy+1 <= 221: rows 0,1 always valid
    bool rv2 = (oy + 2) < OUT;     // false only in last y-tile
    bool rv3 = (oy + 3) < OUT;

    // register-resident input pairs: rows ly..ly+5, 3 overlapping pairs each
    u64 ip[6][3];
#pragma unroll
    for (int r = 0; r < 6; r++) {
        const u64* p = (const u64*)&s_in[(ly + r) * IMG + ox];   // 8B aligned
        u64 a = p[0], b = p[1];
        float a0, a1, a2, a3;
        unpack2(a, a0, a1);
        unpack2(b, a2, a3);
        ip[r][0] = a;
        ip[r][1] = pack2(a1, a2);
        ip[r][2] = b;
    }

    int n = nm / 3;
    float* outp = out + (size_t)(n * NCH + m * 64) * PLANE_OUT
                      + (size_t)oy * OUT + ox;

    for (int c = 0; c < 64; c++) {
        u64 wv[9];
#pragma unroll
        for (int j = 0; j < 9; j++) wv[j] = s_w[c * 9 + j];

        u64 acc0 = 0, acc1 = 0, acc2 = 0, acc3 = 0;
#pragma unroll
        for (int dy = 0; dy < 3; dy++) {
#pragma unroll
            for (int dx = 0; dx < 3; dx++) {
                u64 wt = wv[dy * 3 + dx];
                acc0 = ffma2(ip[0 + dy][dx], wt, acc0);
                acc1 = ffma2(ip[1 + dy][dx], wt, acc1);
                acc2 = ffma2(ip[2 + dy][dx], wt, acc2);
                acc3 = ffma2(ip[3 + dy][dx], wt, acc3);
            }
        }
        *(u64*)(outp)                    = acc0;
        *(u64*)(outp + OUT)              = acc1;
        if (rv2) *(u64*)(outp + 2 * OUT) = acc2;
        if (rv3) *(u64*)(outp + 3 * OUT) = acc3;
        outp += PLANE_OUT;
    }
}

// ===================== launch =====================
extern "C" void kernel_launch(void* const* d_in, const int* in_sizes, int n_in,
                              void* d_out, int out_size) {
    const float* x = (const float*)d_in[0];
    const float* w = (const float*)d_in[1];
    float* out = (float*)d_out;

    rotw_kernel<<<7, 256>>>(w);

    dim3 grid(1,
              (OUT + TH - 1) / TH,   // 28 full-width row tiles
              32 * 3);               // 96 (n,m) planes
    conv_kernel<<<grid, 224>>>(x, out);
}